// round 10
// baseline (speedup 1.0000x reference)
#include <cuda_runtime.h>
#include <cuda_bf16.h>
#include <cuda_fp8.h>
#include <cstdint>

// ============================================================================
// x [M,K] float32 (bf16-valued), weight [N,K] float32 (bf16-valued)
//   -> out [M,N] float32 = (e4m3(sparsify24(x)) @ e4m3(w)^T) * xs * ws
// (harness promotes the reference's bf16 arrays to fp32 at the I/O boundary;
//  the final bf16 cast in the reference is value-preserved in fp32 compare —
//  we reproduce it exactly by rounding through bf16 before the fp32 store)
// e4m3 values are exact in bf16 -> quantized values stored AS bf16, GEMM via
// mma.sync.m16n8k16.bf16 with fp32 accumulation.
// ============================================================================
#define DIM_M 8192
#define DIM_K 4096
#define DIM_N 4096

__device__ __align__(1024) __nv_bfloat16 g_xqb[(size_t)DIM_M * DIM_K]; // 64 MB
__device__ __align__(1024) __nv_bfloat16 g_wqb[(size_t)DIM_N * DIM_K]; // 32 MB
__device__ float g_xs[DIM_M];
__device__ float g_ws[DIM_N];

// ============================================================================
// PTX helpers (plain-target)
// ============================================================================
__device__ __forceinline__ uint32_t smem_to_u32(const void* p) {
    uint32_t a;
    asm("{ .reg .u64 t; cvta.to.shared.u64 t, %1; cvt.u32.u64 %0, t; }"
        : "=r"(a) : "l"(p));
    return a;
}

__device__ __forceinline__ void cp_async16(uint32_t saddr, const void* gaddr) {
    asm volatile("cp.async.cg.shared.global [%0], [%1], 16;\n"
                 :: "r"(saddr), "l"(gaddr));
}
#define CP_COMMIT() asm volatile("cp.async.commit_group;\n" ::: "memory")
#define CP_WAIT_1() asm volatile("cp.async.wait_group 1;\n" ::: "memory")

__device__ __forceinline__ uint32_t lds32(uint32_t addr) {
    uint32_t v;
    asm volatile("ld.shared.b32 %0, [%1];\n" : "=r"(v) : "r"(addr));
    return v;
}

// D += A(bf16, m16 x k16, row) * B(bf16, k16 x n8, col) ; f32 accum
__device__ __forceinline__ void mma_bf16(float* c, const uint32_t* a,
                                         uint32_t b0, uint32_t b1) {
    asm volatile(
        "mma.sync.aligned.m16n8k16.row.col.f32.bf16.bf16.f32 "
        "{%0,%1,%2,%3}, {%4,%5,%6,%7}, {%8,%9}, {%0,%1,%2,%3};\n"
        : "+f"(c[0]), "+f"(c[1]), "+f"(c[2]), "+f"(c[3])
        : "r"(a[0]), "r"(a[1]), "r"(a[2]), "r"(a[3]), "r"(b0), "r"(b1));
}

// float -> e4m3(RN,satfinite) -> exact bf16 of that e4m3 value
__device__ __forceinline__ __nv_bfloat16 quant_e4m3_as_bf16(float v) {
    uint8_t q = (uint8_t)__nv_cvt_float_to_fp8(v, __NV_SATFINITE, __NV_E4M3);
    __half_raw hr = __nv_cvt_fp8_to_halfraw(q, __NV_E4M3);   // exact
    float f = __half2float(*reinterpret_cast<__half*>(&hr)); // exact
    return __float2bfloat16(f);                              // exact (<=4 sig bits)
}

// final value: round through bf16 (reference casts to bf16), return as fp32
__device__ __forceinline__ float round_bf16(float v) {
    return __bfloat162float(__float2bfloat16(v));
}

// ============================================================================
// Kernel 1: rowwise e4m3 quant of weight [N,K] (float32 in, bf16 values out)
// ============================================================================
__global__ __launch_bounds__(128) void quant_w_kernel(const float* __restrict__ w) {
    int row = blockIdx.x;
    int t = threadIdx.x;
    const float* rp = w + (size_t)row * DIM_K;

    float v[32];
    float amax = 0.0f;
#pragma unroll
    for (int i = 0; i < 32; i++) {
        v[i] = rp[t + i * 128];
        amax = fmaxf(amax, fabsf(v[i]));
    }
#pragma unroll
    for (int o = 16; o; o >>= 1) amax = fmaxf(amax, __shfl_xor_sync(0xFFFFFFFFu, amax, o));
    __shared__ float red[4];
    if ((t & 31) == 0) red[t >> 5] = amax;
    __syncthreads();
    float am = fmaxf(fmaxf(red[0], red[1]), fmaxf(red[2], red[3]));
    float scale = __fdiv_rn(fmaxf(am, 1e-12f), 448.0f);

    __nv_bfloat16* qp = g_wqb + (size_t)row * DIM_K;
#pragma unroll
    for (int i = 0; i < 32; i++)
        qp[t + i * 128] = quant_e4m3_as_bf16(__fdiv_rn(v[i], scale));
    if (t == 0) g_ws[row] = scale;
}

// ============================================================================
// Kernel 2: 2:4 sparsify + rowwise e4m3 quant of x [M,K] (float32 in)
// Keep top-2 |v| per group of 4 (stable ties: lower index). Dense amax ==
// sparsified amax (the group max always survives).
// ============================================================================
__global__ __launch_bounds__(128) void quant_x_kernel(const float* __restrict__ x) {
    int row = blockIdx.x;
    int t = threadIdx.x;
    const float* rp = x + (size_t)row * DIM_K;

    float v[8][4];
    float amax = 0.0f;
#pragma unroll
    for (int i = 0; i < 8; i++) {
        int gi = t + i * 128;
        float4 raw = *reinterpret_cast<const float4*>(rp + 4 * gi);
        v[i][0] = raw.x; v[i][1] = raw.y; v[i][2] = raw.z; v[i][3] = raw.w;
#pragma unroll
        for (int j = 0; j < 4; j++) amax = fmaxf(amax, fabsf(v[i][j]));
    }
#pragma unroll
    for (int o = 16; o; o >>= 1) amax = fmaxf(amax, __shfl_xor_sync(0xFFFFFFFFu, amax, o));
    __shared__ float red[4];
    if ((t & 31) == 0) red[t >> 5] = amax;
    __syncthreads();
    float am = fmaxf(fmaxf(red[0], red[1]), fmaxf(red[2], red[3]));
    float scale = __fdiv_rn(fmaxf(am, 1e-12f), 448.0f);

    uint2* qp = reinterpret_cast<uint2*>(g_xqb + (size_t)row * DIM_K);
#pragma unroll
    for (int i = 0; i < 8; i++) {
        int gi = t + i * 128;
        float a[4];
#pragma unroll
        for (int j = 0; j < 4; j++) a[j] = fabsf(v[i][j]);
        unsigned short h[4];
#pragma unroll
        for (int j = 0; j < 4; j++) {
            int rank = 0;
#pragma unroll
            for (int k = 0; k < 4; k++)
                if (k != j && (a[k] > a[j] || (a[k] == a[j] && k < j))) rank++;
            if (rank < 2) {
                __nv_bfloat16 b = quant_e4m3_as_bf16(__fdiv_rn(v[i][j], scale));
                h[j] = reinterpret_cast<__nv_bfloat16_raw&>(b).x;
            } else {
                h[j] = 0;
            }
        }
        uint2 packed;
        packed.x = (uint32_t)h[0] | ((uint32_t)h[1] << 16);
        packed.y = (uint32_t)h[2] | ((uint32_t)h[3] << 16);
        qp[gi] = packed;
    }
    if (t == 0) g_xs[row] = scale;
}

// ============================================================================
// Kernel 3: bf16 GEMM via mma.sync m16n8k16 + fused scaling epilogue (fp32 out)
// CTA tile 128(M) x 256(N), 256 threads = 8 warps (2m x 4n), warp tile 64x64.
// K chunk per stage: 64 elements (128 bytes); 3-stage cp.async pipeline.
// PITCH 144 bytes -> lane word-bank = 4g+tg (permutation) -> conflict-free.
// ============================================================================
#define TILE_M 128
#define TILE_N 256
#define KC     64
#define NKIT   (DIM_K / KC)    /* 64 */
#define STAGES 3
#define PITCH  144

static constexpr uint32_t A_BYTES     = TILE_M * PITCH;            // 18432
static constexpr uint32_t B_BYTES     = TILE_N * PITCH;            // 36864
static constexpr uint32_t STAGE_BYTES = A_BYTES + B_BYTES;         // 55296
static constexpr uint32_t DSMEM_TOTAL = STAGES * STAGE_BYTES;      // 165888

__device__ __forceinline__ void issue_stage(uint32_t stage_base, int kc_elem,
                                            int tile_m, int tile_n, int tid) {
#pragma unroll
    for (int j = 0; j < 12; j++) {
        int id = tid + j * 256;          // 0..3071 chunks of 16B
        uint32_t saddr;
        const __nv_bfloat16* gp;
        if (id < 1024) {                 // A: 128 rows x 8 chunks of 16B
            int row = id >> 3, ch = id & 7;
            saddr = stage_base + row * PITCH + ch * 16;
            gp = g_xqb + (size_t)(tile_m + row) * DIM_K + kc_elem + ch * 8;
        } else {                         // B: 256 rows x 8 chunks of 16B
            int id2 = id - 1024;
            int row = id2 >> 3, ch = id2 & 7;
            saddr = stage_base + A_BYTES + row * PITCH + ch * 16;
            gp = g_wqb + (size_t)(tile_n + row) * DIM_K + kc_elem + ch * 8;
        }
        cp_async16(saddr, gp);
    }
}

__global__ __launch_bounds__(256, 1) void gemm_kernel(float* __restrict__ out) {
    extern __shared__ uint8_t dynsmem[];
    __shared__ float xs_s[TILE_M];
    __shared__ float ws_s[TILE_N];

    uint32_t sbase = smem_to_u32(dynsmem);
    int tid  = threadIdx.x;
    int wid  = tid >> 5;
    int lane = tid & 31;
    int g    = lane >> 2;   // groupID (0..7)
    int tg   = lane & 3;    // threadID_in_group (0..3)
    int wm = wid >> 2;      // 0..1
    int wn = wid & 3;       // 0..3
    int m0 = wm * 64;
    int n0 = wn * 64;
    int tile_m = blockIdx.y * TILE_M;
    int tile_n = blockIdx.x * TILE_N;

    if (tid < TILE_M) xs_s[tid] = g_xs[tile_m + tid];
    ws_s[tid] = g_ws[tile_n + tid];

    float c[4][8][4];
#pragma unroll
    for (int i = 0; i < 4; i++)
#pragma unroll
        for (int j = 0; j < 8; j++)
#pragma unroll
            for (int e = 0; e < 4; e++) c[i][j][e] = 0.0f;

#pragma unroll
    for (int s = 0; s < STAGES - 1; s++) {
        issue_stage(sbase + s * STAGE_BYTES, s * KC, tile_m, tile_n, tid);
        CP_COMMIT();
    }

    for (int i = 0; i < NKIT; i++) {
        CP_WAIT_1();
        __syncthreads();

        uint32_t a_s = sbase + (uint32_t)(i % STAGES) * STAGE_BYTES;
        uint32_t b_s = a_s + A_BYTES;

#pragma unroll
        for (int kc = 0; kc < 4; kc++) {
            int koff = kc * 32 + tg * 4;   // this thread's k-byte base

            // A fragments (m16n8k16 bf16, PTX-spec coords):
            //  a0=(row g, cols 2tg..+1) a1=(row g+8, same) a2/a3 = cols +8
            uint32_t af[4][4];
#pragma unroll
            for (int mt = 0; mt < 4; mt++) {
                uint32_t rbase = a_s + (uint32_t)(m0 + mt * 16 + g) * PITCH + koff;
                af[mt][0] = lds32(rbase);
                af[mt][1] = lds32(rbase + 8 * PITCH);
                af[mt][2] = lds32(rbase + 16);
                af[mt][3] = lds32(rbase + 8 * PITCH + 16);
            }

            // B: b0=(k 2tg..+1 | n g), b1=(k 2tg+8..+9 | n g); col-major==W rows
#pragma unroll
            for (int nt = 0; nt < 8; nt++) {
                uint32_t nbase = b_s + (uint32_t)(n0 + nt * 8 + g) * PITCH + koff;
                uint32_t b0 = lds32(nbase);
                uint32_t b1 = lds32(nbase + 16);
#pragma unroll
                for (int mt = 0; mt < 4; mt++)
                    mma_bf16(c[mt][nt], af[mt], b0, b1);
            }
        }

        int nxt = i + STAGES - 1;
        if (nxt < NKIT)
            issue_stage(sbase + (uint32_t)(nxt % STAGES) * STAGE_BYTES,
                        nxt * KC, tile_m, tile_n, tid);
        CP_COMMIT();   // always commit: wait_group count stays exact in tail
    }

    // epilogue: scale, round through bf16 (reference casts), store FP32
#pragma unroll
    for (int mt = 0; mt < 4; mt++) {
        int rl = m0 + mt * 16 + g;
        float xs0 = xs_s[rl];
        float xs1 = xs_s[rl + 8];
        size_t gr0 = (size_t)(tile_m + rl) * DIM_N + tile_n;
        size_t gr1 = (size_t)(tile_m + rl + 8) * DIM_N + tile_n;
#pragma unroll
        for (int nt = 0; nt < 8; nt++) {
            int cl = n0 + nt * 8 + tg * 2;
            float w0 = ws_s[cl];
            float w1 = ws_s[cl + 1];
            float* cc = c[mt][nt];
            float2 r0, r1;
            r0.x = round_bf16(__fmul_rn(__fmul_rn(cc[0], xs0), w0));
            r0.y = round_bf16(__fmul_rn(__fmul_rn(cc[1], xs0), w1));
            r1.x = round_bf16(__fmul_rn(__fmul_rn(cc[2], xs1), w0));
            r1.y = round_bf16(__fmul_rn(__fmul_rn(cc[3], xs1), w1));
            *reinterpret_cast<float2*>(out + gr0 + cl) = r0;
            *reinterpret_cast<float2*>(out + gr1 + cl) = r1;
        }
    }
}

// ============================================================================
// Host launch — inputs FLOAT32 (bf16-valued); output FLOAT32. x = larger input.
// ============================================================================
extern "C" void kernel_launch(void* const* d_in, const int* in_sizes, int n_in,
                              void* d_out, int out_size) {
    const float* x;
    const float* w;
    if (in_sizes[0] >= in_sizes[1]) {
        x = (const float*)d_in[0];
        w = (const float*)d_in[1];
    } else {
        x = (const float*)d_in[1];
        w = (const float*)d_in[0];
    }
    float* out = (float*)d_out;

    quant_w_kernel<<<DIM_N, 128>>>(w);
    quant_x_kernel<<<DIM_M, 128>>>(x);

    cudaFuncSetAttribute(gemm_kernel, cudaFuncAttributeMaxDynamicSharedMemorySize,
                         DSMEM_TOTAL);
    dim3 grid(DIM_N / TILE_N, DIM_M / TILE_M);  // (16, 64)
    gemm_kernel<<<grid, 256, DSMEM_TOTAL>>>(out);
}

// round 11
// speedup vs baseline: 1.4002x; 1.4002x over previous
#include <cuda_runtime.h>
#include <cuda_bf16.h>
#include <cuda_fp8.h>
#include <cstdint>

// ============================================================================
// x [M,K] float32 (bf16-valued), weight [N,K] float32 (bf16-valued)
//   -> out [M,N] float32 = bf16_round((e4m3(sparsify24(x)) @ e4m3(w)^T)*xs*ws)
// FP8 core: mma.sync.m16n8k32.e4m3 with f32 accum (exact products, fp32 sums).
// ============================================================================
#define DIM_M 8192
#define DIM_K 4096
#define DIM_N 4096

__device__ __align__(1024) uint8_t g_xq[(size_t)DIM_M * DIM_K];   // 32 MB e4m3
__device__ __align__(1024) uint8_t g_wq[(size_t)DIM_N * DIM_K];   // 16 MB e4m3
__device__ float g_xs[DIM_M];
__device__ float g_ws[DIM_N];

// ============================================================================
// PTX helpers (plain-target)
// ============================================================================
__device__ __forceinline__ uint32_t smem_to_u32(const void* p) {
    uint32_t a;
    asm("{ .reg .u64 t; cvta.to.shared.u64 t, %1; cvt.u32.u64 %0, t; }"
        : "=r"(a) : "l"(p));
    return a;
}

__device__ __forceinline__ void cp_async16(uint32_t saddr, const void* gaddr) {
    asm volatile("cp.async.cg.shared.global [%0], [%1], 16;\n"
                 :: "r"(saddr), "l"(gaddr));
}
#define CP_COMMIT() asm volatile("cp.async.commit_group;\n" ::: "memory")
#define CP_WAIT_1() asm volatile("cp.async.wait_group 1;\n" ::: "memory")

__device__ __forceinline__ uint32_t lds32(uint32_t addr) {
    uint32_t v;
    asm volatile("ld.shared.b32 %0, [%1];\n" : "=r"(v) : "r"(addr));
    return v;
}

// D += A(e4m3, m16 x k32, row) * B(e4m3, k32 x n8, col) ; f32 accum
__device__ __forceinline__ void mma_e4m3(float* c, const uint32_t* a,
                                         uint32_t b0, uint32_t b1) {
    asm volatile(
        "mma.sync.aligned.m16n8k32.row.col.f32.e4m3.e4m3.f32 "
        "{%0,%1,%2,%3}, {%4,%5,%6,%7}, {%8,%9}, {%0,%1,%2,%3};\n"
        : "+f"(c[0]), "+f"(c[1]), "+f"(c[2]), "+f"(c[3])
        : "r"(a[0]), "r"(a[1]), "r"(a[2]), "r"(a[3]), "r"(b0), "r"(b1));
}

// final value: round through bf16 (reference casts to bf16), return as fp32
__device__ __forceinline__ float round_bf16(float v) {
    return __bfloat162float(__float2bfloat16(v));
}

__device__ __forceinline__ uint8_t quant_e4m3(float v) {
    return (uint8_t)__nv_cvt_float_to_fp8(v, __NV_SATFINITE, __NV_E4M3);
}

// ============================================================================
// Kernel 1: rowwise e4m3 quant of weight [N,K] (fp32 in, packed e4m3 out)
// ============================================================================
__global__ __launch_bounds__(128) void quant_w_kernel(const float* __restrict__ w) {
    int row = blockIdx.x;
    int t = threadIdx.x;
    const float* rp = w + (size_t)row * DIM_K;

    float v[8][4];
    float amax = 0.0f;
#pragma unroll
    for (int i = 0; i < 8; i++) {
        int gi = t + i * 128;
        float4 raw = *reinterpret_cast<const float4*>(rp + 4 * gi);
        v[i][0] = raw.x; v[i][1] = raw.y; v[i][2] = raw.z; v[i][3] = raw.w;
#pragma unroll
        for (int j = 0; j < 4; j++) amax = fmaxf(amax, fabsf(v[i][j]));
    }
#pragma unroll
    for (int o = 16; o; o >>= 1) amax = fmaxf(amax, __shfl_xor_sync(0xFFFFFFFFu, amax, o));
    __shared__ float red[4];
    if ((t & 31) == 0) red[t >> 5] = amax;
    __syncthreads();
    float am = fmaxf(fmaxf(red[0], red[1]), fmaxf(red[2], red[3]));
    float scale = __fdiv_rn(fmaxf(am, 1e-12f), 448.0f);

    uint32_t* qp = reinterpret_cast<uint32_t*>(g_wq + (size_t)row * DIM_K);
#pragma unroll
    for (int i = 0; i < 8; i++) {
        int gi = t + i * 128;
        uint32_t packed = 0;
#pragma unroll
        for (int j = 0; j < 4; j++)
            packed |= (uint32_t)quant_e4m3(__fdiv_rn(v[i][j], scale)) << (j * 8);
        qp[gi] = packed;
    }
    if (t == 0) g_ws[row] = scale;
}

// ============================================================================
// Kernel 2: 2:4 sparsify + rowwise e4m3 quant of x [M,K] (fp32 in, packed out)
// Keep top-2 |v| per group of 4 (stable ties: lower index). Dense amax ==
// sparsified amax (the group max always survives).
// ============================================================================
__global__ __launch_bounds__(128) void quant_x_kernel(const float* __restrict__ x) {
    int row = blockIdx.x;
    int t = threadIdx.x;
    const float* rp = x + (size_t)row * DIM_K;

    float v[8][4];
    float amax = 0.0f;
#pragma unroll
    for (int i = 0; i < 8; i++) {
        int gi = t + i * 128;
        float4 raw = *reinterpret_cast<const float4*>(rp + 4 * gi);
        v[i][0] = raw.x; v[i][1] = raw.y; v[i][2] = raw.z; v[i][3] = raw.w;
#pragma unroll
        for (int j = 0; j < 4; j++) amax = fmaxf(amax, fabsf(v[i][j]));
    }
#pragma unroll
    for (int o = 16; o; o >>= 1) amax = fmaxf(amax, __shfl_xor_sync(0xFFFFFFFFu, amax, o));
    __shared__ float red[4];
    if ((t & 31) == 0) red[t >> 5] = amax;
    __syncthreads();
    float am = fmaxf(fmaxf(red[0], red[1]), fmaxf(red[2], red[3]));
    float scale = __fdiv_rn(fmaxf(am, 1e-12f), 448.0f);

    uint32_t* qp = reinterpret_cast<uint32_t*>(g_xq + (size_t)row * DIM_K);
#pragma unroll
    for (int i = 0; i < 8; i++) {
        int gi = t + i * 128;
        float a[4];
#pragma unroll
        for (int j = 0; j < 4; j++) a[j] = fabsf(v[i][j]);
        uint32_t packed = 0;
#pragma unroll
        for (int j = 0; j < 4; j++) {
            int rank = 0;
#pragma unroll
            for (int k = 0; k < 4; k++)
                if (k != j && (a[k] > a[j] || (a[k] == a[j] && k < j))) rank++;
            if (rank < 2)
                packed |= (uint32_t)quant_e4m3(__fdiv_rn(v[i][j], scale)) << (j * 8);
        }
        qp[gi] = packed;
    }
    if (t == 0) g_xs[row] = scale;
}

// ============================================================================
// Kernel 3: FP8 GEMM via mma.sync m16n8k32 + fused scaling epilogue (fp32 out)
// CTA tile 128(M) x 256(N), 256 threads = 8 warps (2m x 4n), warp tile 64x64.
// K chunk per stage: 64 bytes; 3-stage cp.async pipeline.
// PITCH 80 -> lane word-bank = (5g+tg) mod 32 (permutation) -> conflict-free.
// ============================================================================
#define TILE_M 128
#define TILE_N 256
#define KC     64
#define NKIT   (DIM_K / KC)   // 64
#define STAGES 3
#define PITCH  80

static constexpr uint32_t A_BYTES     = TILE_M * PITCH;            // 10240
static constexpr uint32_t B_BYTES     = TILE_N * PITCH;            // 20480
static constexpr uint32_t STAGE_BYTES = A_BYTES + B_BYTES;         // 30720
static constexpr uint32_t DSMEM_TOTAL = STAGES * STAGE_BYTES;      // 92160

__device__ __forceinline__ void issue_stage(uint32_t stage_base, int kc_byte,
                                            int tile_m, int tile_n, int tid) {
#pragma unroll
    for (int j = 0; j < 6; j++) {
        int id = tid + j * 256;          // 0..1535 chunks of 16B
        uint32_t saddr;
        const uint8_t* gp;
        if (id < 512) {                  // A: 128 rows x 4 chunks of 16B
            int row = id >> 2, ch = id & 3;
            saddr = stage_base + row * PITCH + ch * 16;
            gp = g_xq + (size_t)(tile_m + row) * DIM_K + kc_byte + ch * 16;
        } else {                         // B: 256 rows x 4 chunks of 16B
            int id2 = id - 512;
            int row = id2 >> 2, ch = id2 & 3;
            saddr = stage_base + A_BYTES + row * PITCH + ch * 16;
            gp = g_wq + (size_t)(tile_n + row) * DIM_K + kc_byte + ch * 16;
        }
        cp_async16(saddr, gp);
    }
}

__global__ __launch_bounds__(256, 1) void gemm_kernel(float* __restrict__ out) {
    extern __shared__ uint8_t dynsmem[];
    __shared__ float xs_s[TILE_M];
    __shared__ float ws_s[TILE_N];

    uint32_t sbase = smem_to_u32(dynsmem);
    int tid  = threadIdx.x;
    int wid  = tid >> 5;
    int lane = tid & 31;
    int g    = lane >> 2;   // groupID (0..7)
    int tg   = lane & 3;    // threadID_in_group (0..3)
    int wm = wid >> 2;      // 0..1
    int wn = wid & 3;       // 0..3
    int m0 = wm * 64;
    int n0 = wn * 64;
    int tile_m = blockIdx.y * TILE_M;
    int tile_n = blockIdx.x * TILE_N;

    if (tid < TILE_M) xs_s[tid] = g_xs[tile_m + tid];
    ws_s[tid] = g_ws[tile_n + tid];

    float c[4][8][4];
#pragma unroll
    for (int i = 0; i < 4; i++)
#pragma unroll
        for (int j = 0; j < 8; j++)
#pragma unroll
            for (int e = 0; e < 4; e++) c[i][j][e] = 0.0f;

#pragma unroll
    for (int s = 0; s < STAGES - 1; s++) {
        issue_stage(sbase + s * STAGE_BYTES, s * KC, tile_m, tile_n, tid);
        CP_COMMIT();
    }

    for (int i = 0; i < NKIT; i++) {
        CP_WAIT_1();
        __syncthreads();

        uint32_t a_s = sbase + (uint32_t)(i % STAGES) * STAGE_BYTES;
        uint32_t b_s = a_s + A_BYTES;

#pragma unroll
        for (int kk = 0; kk < 2; kk++) {
            int koff = kk * 32 + tg * 4;   // this thread's k-byte base

            // A fragments (m16n8k32 e4m3, PTX-spec coords):
            //  a0=(row g, k 4tg..+3) a1=(row g+8, same) a2/a3 = k+16
            uint32_t af[4][4];
#pragma unroll
            for (int mt = 0; mt < 4; mt++) {
                uint32_t rbase = a_s + (uint32_t)(m0 + mt * 16 + g) * PITCH + koff;
                af[mt][0] = lds32(rbase);
                af[mt][1] = lds32(rbase + 8 * PITCH);
                af[mt][2] = lds32(rbase + 16);
                af[mt][3] = lds32(rbase + 8 * PITCH + 16);
            }

            // B: b0=(k 4tg..+3 | n g), b1=(k+16 | n g); col-major == W rows
#pragma unroll
            for (int nt = 0; nt < 8; nt++) {
                uint32_t nbase = b_s + (uint32_t)(n0 + nt * 8 + g) * PITCH + koff;
                uint32_t b0 = lds32(nbase);
                uint32_t b1 = lds32(nbase + 16);
#pragma unroll
                for (int mt = 0; mt < 4; mt++)
                    mma_e4m3(c[mt][nt], af[mt], b0, b1);
            }
        }

        int nxt = i + STAGES - 1;
        if (nxt < NKIT)
            issue_stage(sbase + (uint32_t)(nxt % STAGES) * STAGE_BYTES,
                        nxt * KC, tile_m, tile_n, tid);
        CP_COMMIT();   // always commit: wait_group count stays exact in tail
    }

    // epilogue: scale, round through bf16, store FP32
#pragma unroll
    for (int mt = 0; mt < 4; mt++) {
        int rl = m0 + mt * 16 + g;
        float xs0 = xs_s[rl];
        float xs1 = xs_s[rl + 8];
        size_t gr0 = (size_t)(tile_m + rl) * DIM_N + tile_n;
        size_t gr1 = (size_t)(tile_m + rl + 8) * DIM_N + tile_n;
#pragma unroll
        for (int nt = 0; nt < 8; nt++) {
            int cl = n0 + nt * 8 + tg * 2;
            float w0 = ws_s[cl];
            float w1 = ws_s[cl + 1];
            float* cc = c[mt][nt];
            float2 r0, r1;
            r0.x = round_bf16(__fmul_rn(__fmul_rn(cc[0], xs0), w0));
            r0.y = round_bf16(__fmul_rn(__fmul_rn(cc[1], xs0), w1));
            r1.x = round_bf16(__fmul_rn(__fmul_rn(cc[2], xs1), w0));
            r1.y = round_bf16(__fmul_rn(__fmul_rn(cc[3], xs1), w1));
            *reinterpret_cast<float2*>(out + gr0 + cl) = r0;
            *reinterpret_cast<float2*>(out + gr1 + cl) = r1;
        }
    }
}

// ============================================================================
// Host launch — inputs FLOAT32 (bf16-valued); output FLOAT32. x = larger input.
// ============================================================================
extern "C" void kernel_launch(void* const* d_in, const int* in_sizes, int n_in,
                              void* d_out, int out_size) {
    const float* x;
    const float* w;
    if (in_sizes[0] >= in_sizes[1]) {
        x = (const float*)d_in[0];
        w = (const float*)d_in[1];
    } else {
        x = (const float*)d_in[1];
        w = (const float*)d_in[0];
    }
    float* out = (float*)d_out;

    quant_w_kernel<<<DIM_N, 128>>>(w);
    quant_x_kernel<<<DIM_M, 128>>>(x);

    cudaFuncSetAttribute(gemm_kernel, cudaFuncAttributeMaxDynamicSharedMemorySize,
                         DSMEM_TOTAL);
    dim3 grid(DIM_N / TILE_N, DIM_M / TILE_M);  // (16, 64)
    gemm_kernel<<<grid, 256, DSMEM_TOTAL>>>(out);
}

// round 12
// speedup vs baseline: 1.5802x; 1.1286x over previous
#include <cuda_runtime.h>
#include <cuda_bf16.h>
#include <cuda_fp8.h>
#include <cstdint>

// ============================================================================
// x [M,K] float32 (bf16-valued), weight [N,K] float32 (bf16-valued)
//   -> out [M,N] float32 = bf16_round((e4m3(sparsify24(x)) @ e4m3(w)^T)*xs*ws)
// FP8 core: mma.sync.m16n8k32.e4m3, fragments via ldmatrix.x4, 512 threads.
// ============================================================================
#define DIM_M 8192
#define DIM_K 4096
#define DIM_N 4096

__device__ __align__(1024) uint8_t g_xq[(size_t)DIM_M * DIM_K];   // 32 MB e4m3
__device__ __align__(1024) uint8_t g_wq[(size_t)DIM_N * DIM_K];   // 16 MB e4m3
__device__ float g_xs[DIM_M];
__device__ float g_ws[DIM_N];

// ============================================================================
// PTX helpers (plain-target)
// ============================================================================
__device__ __forceinline__ uint32_t smem_to_u32(const void* p) {
    uint32_t a;
    asm("{ .reg .u64 t; cvta.to.shared.u64 t, %1; cvt.u32.u64 %0, t; }"
        : "=r"(a) : "l"(p));
    return a;
}

__device__ __forceinline__ void cp_async16(uint32_t saddr, const void* gaddr) {
    asm volatile("cp.async.cg.shared.global [%0], [%1], 16;\n"
                 :: "r"(saddr), "l"(gaddr));
}
#define CP_COMMIT() asm volatile("cp.async.commit_group;\n" ::: "memory")
#define CP_WAIT_1() asm volatile("cp.async.wait_group 1;\n" ::: "memory")

__device__ __forceinline__ void ldsm_x4(uint32_t* r, uint32_t addr) {
    asm volatile("ldmatrix.sync.aligned.m8n8.x4.shared.b16 {%0,%1,%2,%3}, [%4];\n"
                 : "=r"(r[0]), "=r"(r[1]), "=r"(r[2]), "=r"(r[3]) : "r"(addr));
}

// D += A(e4m3, m16 x k32, row) * B(e4m3, k32 x n8, col) ; f32 accum
__device__ __forceinline__ void mma_e4m3(float* c, const uint32_t* a,
                                         uint32_t b0, uint32_t b1) {
    asm volatile(
        "mma.sync.aligned.m16n8k32.row.col.f32.e4m3.e4m3.f32 "
        "{%0,%1,%2,%3}, {%4,%5,%6,%7}, {%8,%9}, {%0,%1,%2,%3};\n"
        : "+f"(c[0]), "+f"(c[1]), "+f"(c[2]), "+f"(c[3])
        : "r"(a[0]), "r"(a[1]), "r"(a[2]), "r"(a[3]), "r"(b0), "r"(b1));
}

__device__ __forceinline__ float round_bf16(float v) {
    return __bfloat162float(__float2bfloat16(v));
}

__device__ __forceinline__ uint8_t quant_e4m3(float v) {
    return (uint8_t)__nv_cvt_float_to_fp8(v, __NV_SATFINITE, __NV_E4M3);
}

// ============================================================================
// Kernel 1: rowwise e4m3 quant of weight [N,K] (fp32 in, packed e4m3 out)
// ============================================================================
__global__ __launch_bounds__(128) void quant_w_kernel(const float* __restrict__ w) {
    int row = blockIdx.x;
    int t = threadIdx.x;
    const float* rp = w + (size_t)row * DIM_K;

    float v[8][4];
    float amax = 0.0f;
#pragma unroll
    for (int i = 0; i < 8; i++) {
        int gi = t + i * 128;
        float4 raw = *reinterpret_cast<const float4*>(rp + 4 * gi);
        v[i][0] = raw.x; v[i][1] = raw.y; v[i][2] = raw.z; v[i][3] = raw.w;
#pragma unroll
        for (int j = 0; j < 4; j++) amax = fmaxf(amax, fabsf(v[i][j]));
    }
#pragma unroll
    for (int o = 16; o; o >>= 1) amax = fmaxf(amax, __shfl_xor_sync(0xFFFFFFFFu, amax, o));
    __shared__ float red[4];
    if ((t & 31) == 0) red[t >> 5] = amax;
    __syncthreads();
    float am = fmaxf(fmaxf(red[0], red[1]), fmaxf(red[2], red[3]));
    float scale = __fdiv_rn(fmaxf(am, 1e-12f), 448.0f);

    uint32_t* qp = reinterpret_cast<uint32_t*>(g_wq + (size_t)row * DIM_K);
#pragma unroll
    for (int i = 0; i < 8; i++) {
        int gi = t + i * 128;
        uint32_t packed = 0;
#pragma unroll
        for (int j = 0; j < 4; j++)
            packed |= (uint32_t)quant_e4m3(__fdiv_rn(v[i][j], scale)) << (j * 8);
        qp[gi] = packed;
    }
    if (t == 0) g_ws[row] = scale;
}

// ============================================================================
// Kernel 2: 2:4 sparsify + rowwise e4m3 quant of x [M,K] (fp32 in, packed out)
// ============================================================================
__global__ __launch_bounds__(128) void quant_x_kernel(const float* __restrict__ x) {
    int row = blockIdx.x;
    int t = threadIdx.x;
    const float* rp = x + (size_t)row * DIM_K;

    float v[8][4];
    float amax = 0.0f;
#pragma unroll
    for (int i = 0; i < 8; i++) {
        int gi = t + i * 128;
        float4 raw = *reinterpret_cast<const float4*>(rp + 4 * gi);
        v[i][0] = raw.x; v[i][1] = raw.y; v[i][2] = raw.z; v[i][3] = raw.w;
#pragma unroll
        for (int j = 0; j < 4; j++) amax = fmaxf(amax, fabsf(v[i][j]));
    }
#pragma unroll
    for (int o = 16; o; o >>= 1) amax = fmaxf(amax, __shfl_xor_sync(0xFFFFFFFFu, amax, o));
    __shared__ float red[4];
    if ((t & 31) == 0) red[t >> 5] = amax;
    __syncthreads();
    float am = fmaxf(fmaxf(red[0], red[1]), fmaxf(red[2], red[3]));
    float scale = __fdiv_rn(fmaxf(am, 1e-12f), 448.0f);

    uint32_t* qp = reinterpret_cast<uint32_t*>(g_xq + (size_t)row * DIM_K);
#pragma unroll
    for (int i = 0; i < 8; i++) {
        int gi = t + i * 128;
        float a[4];
#pragma unroll
        for (int j = 0; j < 4; j++) a[j] = fabsf(v[i][j]);
        uint32_t packed = 0;
#pragma unroll
        for (int j = 0; j < 4; j++) {
            int rank = 0;
#pragma unroll
            for (int k = 0; k < 4; k++)
                if (k != j && (a[k] > a[j] || (a[k] == a[j] && k < j))) rank++;
            if (rank < 2)
                packed |= (uint32_t)quant_e4m3(__fdiv_rn(v[i][j], scale)) << (j * 8);
        }
        qp[gi] = packed;
    }
    if (t == 0) g_xs[row] = scale;
}

// ============================================================================
// Kernel 3: FP8 GEMM. CTA tile 128x256, 512 threads = 16 warps (4m x 4n),
// warp tile 32x64. K chunk 64 bytes; 3-stage cp.async; ldmatrix fragments.
// PITCH 80 -> ldmatrix row chunks hit banks 5r mod 8 (permutation): no conflicts.
// ============================================================================
#define TILE_M 128
#define TILE_N 256
#define KC     64
#define NKIT   (DIM_K / KC)   // 64
#define STAGES 3
#define PITCH  80
#define NTHREADS 512

static constexpr uint32_t A_BYTES     = TILE_M * PITCH;            // 10240
static constexpr uint32_t B_BYTES     = TILE_N * PITCH;            // 20480
static constexpr uint32_t STAGE_BYTES = A_BYTES + B_BYTES;         // 30720
static constexpr uint32_t DSMEM_TOTAL = STAGES * STAGE_BYTES;      // 92160

__device__ __forceinline__ void issue_stage(uint32_t stage_base, int kc_byte,
                                            int tile_m, int tile_n, int tid) {
#pragma unroll
    for (int j = 0; j < 3; j++) {
        int id = tid + j * NTHREADS;     // 0..1535 chunks of 16B
        uint32_t saddr;
        const uint8_t* gp;
        if (id < 512) {                  // A: 128 rows x 4 chunks of 16B
            int row = id >> 2, ch = id & 3;
            saddr = stage_base + row * PITCH + ch * 16;
            gp = g_xq + (size_t)(tile_m + row) * DIM_K + kc_byte + ch * 16;
        } else {                         // B: 256 rows x 4 chunks of 16B
            int id2 = id - 512;
            int row = id2 >> 2, ch = id2 & 3;
            saddr = stage_base + A_BYTES + row * PITCH + ch * 16;
            gp = g_wq + (size_t)(tile_n + row) * DIM_K + kc_byte + ch * 16;
        }
        cp_async16(saddr, gp);
    }
}

__global__ __launch_bounds__(NTHREADS, 1) void gemm_kernel(float* __restrict__ out) {
    extern __shared__ uint8_t dynsmem[];
    __shared__ float xs_s[TILE_M];
    __shared__ float ws_s[TILE_N];

    uint32_t sbase = smem_to_u32(dynsmem);
    int tid  = threadIdx.x;
    int wid  = tid >> 5;
    int lane = tid & 31;
    int g    = lane >> 2;   // groupID (0..7)
    int tg   = lane & 3;    // threadID_in_group (0..3)
    int wm = wid >> 2;      // 0..3
    int wn = wid & 3;       // 0..3
    int m0 = wm * 32;
    int n0 = wn * 64;
    int tile_m = blockIdx.y * TILE_M;
    int tile_n = blockIdx.x * TILE_N;

    if (tid < TILE_M) xs_s[tid] = g_xs[tile_m + tid];
    if (tid < TILE_N) ws_s[tid] = g_ws[tile_n + tid];

    float c[2][8][4];
#pragma unroll
    for (int i = 0; i < 2; i++)
#pragma unroll
        for (int j = 0; j < 8; j++)
#pragma unroll
            for (int e = 0; e < 4; e++) c[i][j][e] = 0.0f;

#pragma unroll
    for (int s = 0; s < STAGES - 1; s++) {
        issue_stage(sbase + s * STAGE_BYTES, s * KC, tile_m, tile_n, tid);
        CP_COMMIT();
    }

    // ldmatrix lane address components (validated mapping):
    // A x4: lanes 0-15 -> rows 0-15 at +0; lanes 16-31 -> rows 0-15 at +16
    //   => regs [r0-7@k0-15, r8-15@k0-15, r0-7@k16-31, r8-15@k16-31] = a0..a3
    int a_row_off = (lane & 15) * PITCH + (lane >> 4) * 16;
    // B x4 over 16 n-rows: [n0-7@k0-15, n0-7@k16-31, n8-15@k0-15, n8-15@k16-31]
    int b_row_off = ((lane & 7) + (lane >> 4) * 8) * PITCH + ((lane >> 3) & 1) * 16;

    for (int i = 0; i < NKIT; i++) {
        CP_WAIT_1();
        __syncthreads();

        uint32_t a_s = sbase + (uint32_t)(i % STAGES) * STAGE_BYTES;
        uint32_t b_s = a_s + A_BYTES;

#pragma unroll
        for (int kk = 0; kk < 2; kk++) {
            int koff = kk * 32;
            uint32_t af[2][4], bf[4][4];
#pragma unroll
            for (int mt = 0; mt < 2; mt++)
                ldsm_x4(af[mt], a_s + (m0 + mt * 16) * PITCH + koff + a_row_off);
#pragma unroll
            for (int ng = 0; ng < 4; ng++)
                ldsm_x4(bf[ng], b_s + (n0 + ng * 16) * PITCH + koff + b_row_off);
#pragma unroll
            for (int mt = 0; mt < 2; mt++)
#pragma unroll
                for (int nt = 0; nt < 8; nt++)
                    mma_e4m3(c[mt][nt], af[mt],
                             bf[nt >> 1][(nt & 1) * 2], bf[nt >> 1][(nt & 1) * 2 + 1]);
        }

        int nxt = i + STAGES - 1;
        if (nxt < NKIT)
            issue_stage(sbase + (uint32_t)(nxt % STAGES) * STAGE_BYTES,
                        nxt * KC, tile_m, tile_n, tid);
        CP_COMMIT();   // always commit: wait_group count stays exact in tail
    }

    // epilogue: scale, round through bf16, store FP32
#pragma unroll
    for (int mt = 0; mt < 2; mt++) {
        int rl = m0 + mt * 16 + g;
        float xs0 = xs_s[rl];
        float xs1 = xs_s[rl + 8];
        size_t gr0 = (size_t)(tile_m + rl) * DIM_N + tile_n;
        size_t gr1 = (size_t)(tile_m + rl + 8) * DIM_N + tile_n;
#pragma unroll
        for (int nt = 0; nt < 8; nt++) {
            int cl = n0 + nt * 8 + tg * 2;
            float w0 = ws_s[cl];
            float w1 = ws_s[cl + 1];
            float* cc = c[mt][nt];
            float2 r0, r1;
            r0.x = round_bf16(__fmul_rn(__fmul_rn(cc[0], xs0), w0));
            r0.y = round_bf16(__fmul_rn(__fmul_rn(cc[1], xs0), w1));
            r1.x = round_bf16(__fmul_rn(__fmul_rn(cc[2], xs1), w0));
            r1.y = round_bf16(__fmul_rn(__fmul_rn(cc[3], xs1), w1));
            *reinterpret_cast<float2*>(out + gr0 + cl) = r0;
            *reinterpret_cast<float2*>(out + gr1 + cl) = r1;
        }
    }
}

// ============================================================================
// Host launch — inputs FLOAT32 (bf16-valued); output FLOAT32. x = larger input.
// ============================================================================
extern "C" void kernel_launch(void* const* d_in, const int* in_sizes, int n_in,
                              void* d_out, int out_size) {
    const float* x;
    const float* w;
    if (in_sizes[0] >= in_sizes[1]) {
        x = (const float*)d_in[0];
        w = (const float*)d_in[1];
    } else {
        x = (const float*)d_in[1];
        w = (const float*)d_in[0];
    }
    float* out = (float*)d_out;

    quant_w_kernel<<<DIM_N, 128>>>(w);
    quant_x_kernel<<<DIM_M, 128>>>(x);

    cudaFuncSetAttribute(gemm_kernel, cudaFuncAttributeMaxDynamicSharedMemorySize,
                         DSMEM_TOTAL);
    dim3 grid(DIM_N / TILE_N, DIM_M / TILE_M);  // (16, 64)
    gemm_kernel<<<grid, NTHREADS, DSMEM_TOTAL>>>(out);
}